// round 3
// baseline (speedup 1.0000x reference)
#include <cuda_runtime.h>

#define IMG 1024
#define HW (IMG*IMG)
#define NB 16
#define TILE 64
#define HALO 8
#define PAD 80            // TILE + 2*HALO
#define NTH 256
#define HROWS 66          // rows needed in horizontal-max buffer

// ping-pong eroded-image scratch (static device arrays: allowed)
__device__ float g_e0[(size_t)NB * HW];
__device__ float g_e1[(size_t)NB * HW];

__global__ void __launch_bounds__(NTH, 2)
skel_kernel(const float* __restrict__ img, float* __restrict__ sk,
            int insel, int outsel, int nsteps, int first)
{
    extern __shared__ float sm[];
    float* sA = sm;                    // PAD*PAD = 6400 floats
    float* sB = sm + PAD * PAD;        // 6400 floats
    float* hb = sm + 2 * PAD * PAD;    // HROWS*64 = 4224 floats

    const float* ein = (insel == 0) ? img : (insel == 1 ? g_e0 : g_e1);
    float* eout = (outsel == 1) ? g_e0 : g_e1;

    const int b = blockIdx.z;
    const int tx0 = blockIdx.x * TILE, ty0 = blockIdx.y * TILE;
    const int ocol = tx0 - HALO, orow = ty0 - HALO;
    const int t = threadIdx.x;

    const float* inb = ein + (size_t)b * HW;
    float* skb = sk + (size_t)b * HW;
    float* eob = eout + (size_t)b * HW;

    // load padded tile (clamp to image: exact replicate semantics for min/max)
    for (int i = t; i < PAD * PAD; i += NTH) {
        int r = i / PAD, c = i - r * PAD;
        int gr = min(max(orow + r, 0), IMG - 1);
        int gc = min(max(ocol + c, 0), IMG - 1);
        sA[i] = inb[(size_t)gr * IMG + gc];
    }

    // sk accumulator in registers: thread t owns output cells idx = t + 256*k
    float skr[16];
    if (first) {
#pragma unroll
        for (int k = 0; k < 16; ++k) skr[k] = 0.f;
    } else {
#pragma unroll
        for (int k = 0; k < 16; ++k) {
            int idx = t + k * NTH;
            int ro = idx >> 6, co = idx & 63;
            skr[k] = skb[(size_t)(ty0 + ro) * IMG + (tx0 + co)];
        }
    }
    __syncthreads();

    float* scur = sA;   // holds e_k
    float* snx  = sB;   // will hold e_{k+1}

    for (int step = 0; step < nsteps; ++step) {
        // ---- erode (5-point cross min) scur -> snx over full padded tile ----
        for (int i = t; i < PAD * PAD; i += NTH) {
            int r = i / PAD, c = i - r * PAD;
            float cv = scur[i];
            int gr = orow + r, gc = ocol + c;
            float up = (r > 0       && (unsigned)(gr - 1) < IMG) ? scur[i - PAD] : cv;
            float dn = (r < PAD - 1 && (unsigned)(gr + 1) < IMG) ? scur[i + PAD] : cv;
            float lf = (c > 0       && (unsigned)(gc - 1) < IMG) ? scur[i - 1]   : cv;
            float rt = (c < PAD - 1 && (unsigned)(gc + 1) < IMG) ? scur[i + 1]   : cv;
            snx[i] = fminf(fminf(fminf(up, dn), fminf(lf, rt)), cv);
        }
        __syncthreads();

        // ---- horizontal 3-max of snx into hb (buffer rows 7..72, cols 8..71) ----
        for (int i = t; i < HROWS * TILE; i += NTH) {
            int hr = i >> 6, co = i & 63;
            int r = hr + 7, c = co + 8;
            int base = r * PAD + c;
            float cv = snx[base];
            int gc = ocol + c;
            float lf = ((unsigned)(gc - 1) < IMG) ? snx[base - 1] : cv;
            float rt = ((unsigned)(gc + 1) < IMG) ? snx[base + 1] : cv;
            hb[i] = fmaxf(fmaxf(lf, rt), cv);
        }
        __syncthreads();

        // ---- vertical 3-max -> dilate; delta; sk update (output 64x64) ----
#pragma unroll
        for (int k = 0; k < 16; ++k) {
            int idx = t + k * NTH;
            int ro = idx >> 6, co = idx & 63;
            float cm = hb[(ro + 1) * 64 + co];
            int gr = ty0 + ro;   // in-image output row
            float um = ((unsigned)(gr - 1) < IMG) ? hb[ro * 64 + co]       : cm;
            float dm = ((unsigned)(gr + 1) < IMG) ? hb[(ro + 2) * 64 + co] : cm;
            float dil = fmaxf(fmaxf(um, dm), cm);
            float ek  = scur[(ro + 8) * PAD + (co + 8)];   // e_k (pre-erode buffer)
            float delta = fmaxf(ek - dil, 0.f);
            skr[k] = skr[k] + fmaxf(delta - skr[k] * delta, 0.f);
        }
        __syncthreads();

        float* tmp = scur; scur = snx; snx = tmp;  // scur now holds e_{k+1}
    }

    // ---- write sk and e_{start+nsteps} interior ----
#pragma unroll
    for (int k = 0; k < 16; ++k) {
        int idx = t + k * NTH;
        int ro = idx >> 6, co = idx & 63;
        size_t g = (size_t)(ty0 + ro) * IMG + (tx0 + co);
        skb[g] = skr[k];
        eob[g] = scur[(ro + 8) * PAD + (co + 8)];
    }
}

extern "C" void kernel_launch(void* const* d_in, const int* in_sizes, int n_in,
                              void* d_out, int out_size)
{
    const float* img = (const float*)d_in[0];
    float* sk = (float*)d_out;

    const int smem = (2 * PAD * PAD + HROWS * TILE) * 4;  // 68096 bytes
    cudaFuncSetAttribute(skel_kernel,
                         cudaFuncAttributeMaxDynamicSharedMemorySize, smem);

    dim3 grid(IMG / TILE, IMG / TILE, NB);  // 16 x 16 x 16
    dim3 block(NTH);

    // 6 launches: steps 7,7,7,7,7,6  -> 41 deltas total (e_0 .. e_41)
    skel_kernel<<<grid, block, smem>>>(img, sk, 0, 1, 7, 1);
    skel_kernel<<<grid, block, smem>>>(img, sk, 1, 2, 7, 0);
    skel_kernel<<<grid, block, smem>>>(img, sk, 2, 1, 7, 0);
    skel_kernel<<<grid, block, smem>>>(img, sk, 1, 2, 7, 0);
    skel_kernel<<<grid, block, smem>>>(img, sk, 2, 1, 7, 0);
    skel_kernel<<<grid, block, smem>>>(img, sk, 1, 2, 6, 0);
}

// round 4
// speedup vs baseline: 1.4502x; 1.4502x over previous
#include <cuda_runtime.h>

#define IMG   1024
#define HWSZ  (IMG*IMG)
#define NB    16
#define TILE  64
#define HALO  8
#define DATA  80            // padded data region: 80 x 80
#define PADW  84            // row stride in floats (21 float4, odd mod 8)
#define ROWSL 82            // slot 0 guard, 1..80 data, 81 guard
#define BUFSZ (ROWSL*PADW)  // 6888 floats
#define NTH   320
#define FINF  __int_as_float(0x7f800000)

// ping-pong eroded-image scratch (static device arrays: allowed)
__device__ float g_e0[(size_t)NB * HWSZ];
__device__ float g_e1[(size_t)NB * HWSZ];

__global__ void __launch_bounds__(NTH, 2)
skel_kernel(const float* __restrict__ img, float* __restrict__ sk,
            int insel, int outsel, int nsteps, int first)
{
    extern __shared__ float sm[];
    float* sA = sm;
    float* sB = sm + BUFSZ;

    const float* ein  = (insel == 0) ? img : (insel == 1 ? g_e0 : g_e1);
    float*       eout = (outsel == 1) ? g_e0 : g_e1;

    const int b   = blockIdx.z;
    const int tx0 = blockIdx.x * TILE, ty0 = blockIdx.y * TILE;
    const int ocol = tx0 - HALO, orow = ty0 - HALO;
    const int t   = threadIdx.x;

    const float* inb = ein + (size_t)b * HWSZ;
    float*       skb = sk  + (size_t)b * HWSZ;
    float*       eob = eout + (size_t)b * HWSZ;

    const bool btop = (orow < 0),        bbot = (orow + DATA > IMG);
    const bool blft = (ocol < 0),        brgt = (ocol + DATA > IMG);
    const bool bdry = btop | bbot | blft | brgt;

    // ---- init guards (+INF everywhere), then clamped load of data region ----
    for (int i = t; i < BUFSZ; i += NTH) { sA[i] = FINF; sB[i] = FINF; }
    __syncthreads();
    for (int i = t; i < DATA * DATA; i += NTH) {
        int r = i / DATA, c = i - r * DATA;
        int gr = min(max(orow + r, 0), IMG - 1);
        int gc = min(max(ocol + c, 0), IMG - 1);
        sA[(r + 1) * PADW + (c + 4)] = inb[(size_t)gr * IMG + gc];
    }

    // ---- sk accumulator: threads 0..255 own 4x4 output cells each ----
    // vc = t&15 : output float4-col (cols vc*4..vc*4+3); rs2 = t>>4 : rows rs2*4..rs2*4+3
    const int vc  = t & 15;
    const int rs2 = t >> 4;
    const int fc  = 12 + 4 * vc;        // buffer float col of output vec
    const int q0  = rs2 * 4 + 9;        // first output row slot
    float4 skr[4];
    if (t < 256) {
        if (first) {
#pragma unroll
            for (int k = 0; k < 4; ++k) skr[k] = make_float4(0.f, 0.f, 0.f, 0.f);
        } else {
#pragma unroll
            for (int k = 0; k < 4; ++k)
                skr[k] = *(const float4*)(skb + (size_t)(ty0 + rs2 * 4 + k) * IMG + tx0 + vc * 4);
        }
    }

    // ---- erode walk mapping: 20 vec-cols x 16 strips of 5 rows ----
    const int ec4  = t % 20;
    const int ers  = t / 20;
    const int er0  = ers * 5;           // data rows er0..er0+4 -> slots er0+1..er0+5
    const int efc  = 4 + 4 * ec4;

    __syncthreads();

    float* scur = sA;   // e_k
    float* snx  = sB;   // e_{k+1}

    for (int step = 0; step < nsteps; ++step) {
        // ======== erode: 5-point cross min, check-free ========
        {
            const float* sc = scur;
            float* sn = snx;
            float4 up = *(const float4*)(sc + er0 * PADW + efc);
            float4 ce = *(const float4*)(sc + (er0 + 1) * PADW + efc);
#pragma unroll
            for (int k = 0; k < 5; ++k) {
                const int q = er0 + 1 + k;
                float4 dn = *(const float4*)(sc + (q + 1) * PADW + efc);
                float lf  = sc[q * PADW + efc - 1];
                float rt  = sc[q * PADW + efc + 4];
                float4 o;
                o.x = fminf(fminf(ce.x, fminf(up.x, dn.x)), fminf(lf,  ce.y));
                o.y = fminf(fminf(ce.y, fminf(up.y, dn.y)), fminf(ce.x, ce.z));
                o.z = fminf(fminf(ce.z, fminf(up.z, dn.z)), fminf(ce.y, ce.w));
                o.w = fminf(fminf(ce.w, fminf(up.w, dn.w)), fminf(ce.z, rt));
                *(float4*)(sn + q * PADW + efc) = o;
                up = ce; ce = dn;
            }
        }
        __syncthreads();

        // ======== boundary fixup: make snx exactly replicate-padded ========
        if (bdry) {
            if (btop) for (int i = t; i < 8 * DATA; i += NTH) {
                int rr = i / DATA, c = i - rr * DATA;
                snx[(1 + rr) * PADW + 4 + c] = snx[9 * PADW + 4 + c];
            }
            if (bbot) for (int i = t; i < 8 * DATA; i += NTH) {
                int rr = i / DATA, c = i - rr * DATA;
                snx[(73 + rr) * PADW + 4 + c] = snx[72 * PADW + 4 + c];
            }
            __syncthreads();
            if (blft) for (int i = t; i < DATA * 8; i += NTH) {
                int rr = i >> 3, c = i & 7;
                snx[(1 + rr) * PADW + 4 + c] = snx[(1 + rr) * PADW + 12];
            }
            if (brgt) for (int i = t; i < DATA * 8; i += NTH) {
                int rr = i >> 3, c = i & 7;
                snx[(1 + rr) * PADW + 76 + c] = snx[(1 + rr) * PADW + 75];
            }
        }
        __syncthreads();

        // ======== fused dilate(3x3 max) + delta + sk update ========
        if (t < 256) {
            const float* sn = snx;
            const float* sc = scur;
            // rolling horizontal-3-max rows: slots q0-1 .. q0+4
            float4 hA, hB;
            {
                int q = q0 - 1;
                float4 ce = *(const float4*)(sn + q * PADW + fc);
                float lf = sn[q * PADW + fc - 1], rt = sn[q * PADW + fc + 4];
                hA.x = fmaxf(ce.x, fmaxf(lf,  ce.y));
                hA.y = fmaxf(ce.y, fmaxf(ce.x, ce.z));
                hA.z = fmaxf(ce.z, fmaxf(ce.y, ce.w));
                hA.w = fmaxf(ce.w, fmaxf(ce.z, rt));
                q = q0;
                ce = *(const float4*)(sn + q * PADW + fc);
                lf = sn[q * PADW + fc - 1]; rt = sn[q * PADW + fc + 4];
                hB.x = fmaxf(ce.x, fmaxf(lf,  ce.y));
                hB.y = fmaxf(ce.y, fmaxf(ce.x, ce.z));
                hB.z = fmaxf(ce.z, fmaxf(ce.y, ce.w));
                hB.w = fmaxf(ce.w, fmaxf(ce.z, rt));
            }
#pragma unroll
            for (int k = 0; k < 4; ++k) {
                const int q = q0 + k;
                float4 ce = *(const float4*)(sn + (q + 1) * PADW + fc);
                float lf = sn[(q + 1) * PADW + fc - 1], rt = sn[(q + 1) * PADW + fc + 4];
                float4 hC;
                hC.x = fmaxf(ce.x, fmaxf(lf,  ce.y));
                hC.y = fmaxf(ce.y, fmaxf(ce.x, ce.z));
                hC.z = fmaxf(ce.z, fmaxf(ce.y, ce.w));
                hC.w = fmaxf(ce.w, fmaxf(ce.z, rt));
                float4 ek = *(const float4*)(sc + q * PADW + fc);
                float4 d;
                d.x = fmaxf(ek.x - fmaxf(hB.x, fmaxf(hA.x, hC.x)), 0.f);
                d.y = fmaxf(ek.y - fmaxf(hB.y, fmaxf(hA.y, hC.y)), 0.f);
                d.z = fmaxf(ek.z - fmaxf(hB.z, fmaxf(hA.z, hC.z)), 0.f);
                d.w = fmaxf(ek.w - fmaxf(hB.w, fmaxf(hA.w, hC.w)), 0.f);
                skr[k].x += fmaxf(d.x - skr[k].x * d.x, 0.f);
                skr[k].y += fmaxf(d.y - skr[k].y * d.y, 0.f);
                skr[k].z += fmaxf(d.z - skr[k].z * d.z, 0.f);
                skr[k].w += fmaxf(d.w - skr[k].w * d.w, 0.f);
                hA = hB; hB = hC;
            }
        }
        __syncthreads();

        float* tmp = scur; scur = snx; snx = tmp;   // scur now e_{k+1}
    }

    // ---- write sk and final eroded image (interior 64x64) ----
    if (t < 256) {
#pragma unroll
        for (int k = 0; k < 4; ++k) {
            size_t g = (size_t)(ty0 + rs2 * 4 + k) * IMG + tx0 + vc * 4;
            *(float4*)(skb + g) = skr[k];
            *(float4*)(eob + g) = *(const float4*)(scur + (q0 + k) * PADW + fc);
        }
    }
}

extern "C" void kernel_launch(void* const* d_in, const int* in_sizes, int n_in,
                              void* d_out, int out_size)
{
    const float* img = (const float*)d_in[0];
    float* sk = (float*)d_out;

    const int smem = 2 * BUFSZ * (int)sizeof(float);   // 55104 bytes
    cudaFuncSetAttribute(skel_kernel,
                         cudaFuncAttributeMaxDynamicSharedMemorySize, smem);

    dim3 grid(IMG / TILE, IMG / TILE, NB);   // 16 x 16 x 16
    dim3 block(NTH);

    // 6 launches: 7+7+7+7+7+6 = 41 deltas (e_0 .. e_41)
    skel_kernel<<<grid, block, smem>>>(img, sk, 0, 1, 7, 1);
    skel_kernel<<<grid, block, smem>>>(img, sk, 1, 2, 7, 0);
    skel_kernel<<<grid, block, smem>>>(img, sk, 2, 1, 7, 0);
    skel_kernel<<<grid, block, smem>>>(img, sk, 1, 2, 7, 0);
    skel_kernel<<<grid, block, smem>>>(img, sk, 2, 1, 7, 0);
    skel_kernel<<<grid, block, smem>>>(img, sk, 1, 2, 6, 0);
}

// round 5
// speedup vs baseline: 2.5437x; 1.7540x over previous
#include <cuda_runtime.h>

#define IMG   1024
#define HWSZ  (IMG*IMG)
#define NB    16
#define TILE  64
#define HALO  8
#define NX    20          // float4 lanes across (80 cols)
#define NY    16          // row groups
#define RPT   5           // rows per thread (80 rows)
#define NTH   (NX*NY)     // 320
#define SENT  1e30f
#define NEGS  (-1e30f)

// ping-pong eroded-image scratch (static device arrays: allowed)
__device__ float g_e0[(size_t)NB * HWSZ];
__device__ float g_e1[(size_t)NB * HWSZ];

struct SMState {
    float  cw[80][21];      // per-row .w edge scalar of each lane (padded stride)
    float  cx[80][21];      // per-row .x edge scalar
    float4 rtop[NY][NX];    // each thread's row 0
    float4 rbot[NY][NX];    // each thread's row RPT-1
};

__device__ __forceinline__ float4 f4sent() { return make_float4(SENT, SENT, SENT, SENT); }

__device__ __forceinline__ float4 f4min5(float4 ce, float4 up, float4 dn, float lf, float rt) {
    float4 o;
    o.x = fminf(fminf(ce.x, fminf(up.x, dn.x)), fminf(lf,   ce.y));
    o.y = fminf(fminf(ce.y, fminf(up.y, dn.y)), fminf(ce.x, ce.z));
    o.z = fminf(fminf(ce.z, fminf(up.z, dn.z)), fminf(ce.y, ce.w));
    o.w = fminf(fminf(ce.w, fminf(up.w, dn.w)), fminf(ce.z, rt));
    return o;
}

__device__ __forceinline__ float dv(float v)  { return v > 1e29f ? NEGS : v; }
__device__ __forceinline__ float4 dv4(float4 v) {
    return make_float4(dv(v.x), dv(v.y), dv(v.z), dv(v.w));
}

__device__ __forceinline__ float4 hmax4(float4 ce, float lf, float rt) {
    float m01 = fmaxf(ce.x, ce.y), m23 = fmaxf(ce.z, ce.w);
    float4 h;
    h.x = fmaxf(lf,   m01);
    h.y = fmaxf(m01,  ce.z);
    h.z = fmaxf(ce.y, m23);
    h.w = fmaxf(m23,  rt);
    return h;
}

template<bool BDRY>
__device__ __forceinline__ void run_steps(
    int nsteps, SMState& s, float4 (&e)[RPT], float4 (&skr)[RPT],
    int x, int y, int r0, int gc0, int orow)
{
    for (int step = 0; step < nsteps; ++step) {
        // ---- gather e_k neighbors (edges published previously) ----
        float4 up = (y > 0)      ? s.rbot[y-1][x] : f4sent();
        float4 dn = (y < NY - 1) ? s.rtop[y+1][x] : f4sent();
        float lf[RPT], rt[RPT];
#pragma unroll
        for (int r = 0; r < RPT; ++r) {
            lf[r] = (x > 0)      ? s.cw[r0+r][x-1] : SENT;
            rt[r] = (x < NX - 1) ? s.cx[r0+r][x+1] : SENT;
        }
        // ---- erode: 5-point cross min, all in registers ----
        float4 n[RPT];
        n[0] = f4min5(e[0], up,   e[1], lf[0], rt[0]);
        n[1] = f4min5(e[1], e[0], e[2], lf[1], rt[1]);
        n[2] = f4min5(e[2], e[1], e[3], lf[2], rt[2]);
        n[3] = f4min5(e[3], e[2], e[4], lf[3], rt[3]);
        n[4] = f4min5(e[4], e[3], dn,   lf[4], rt[4]);
        if (BDRY) {
            // re-impose +inf sentinel at out-of-image cells (exact erode semantics)
#pragma unroll
            for (int r = 0; r < RPT; ++r) {
                int gr = orow + r0 + r;
                if ((unsigned)gr >= IMG) n[r] = f4sent();
                else {
                    if ((unsigned)(gc0+0) >= IMG) n[r].x = SENT;
                    if ((unsigned)(gc0+1) >= IMG) n[r].y = SENT;
                    if ((unsigned)(gc0+2) >= IMG) n[r].z = SENT;
                    if ((unsigned)(gc0+3) >= IMG) n[r].w = SENT;
                }
            }
        }
        __syncthreads();             // everyone done reading e_k edges
        // ---- publish e_{k+1} edges ----
        s.rtop[y][x] = n[0];
        s.rbot[y][x] = n[RPT-1];
#pragma unroll
        for (int r = 0; r < RPT; ++r) { s.cx[r0+r][x] = n[r].x; s.cw[r0+r][x] = n[r].w; }
        __syncthreads();
        // ---- dilate(3x3 max of e_{k+1}) + delta + sk, rows r0-1 .. r0+5 ----
        float4 nup = (y > 0)      ? s.rbot[y-1][x] : f4sent();
        float4 ndn = (y < NY - 1) ? s.rtop[y+1][x] : f4sent();
        float lfu = (y > 0      && x > 0)      ? s.cw[r0-1][x-1]   : SENT;
        float rtu = (y > 0      && x < NX - 1) ? s.cx[r0-1][x+1]   : SENT;
        float lfd = (y < NY - 1 && x > 0)      ? s.cw[r0+RPT][x-1] : SENT;
        float rtd = (y < NY - 1 && x < NX - 1) ? s.cx[r0+RPT][x+1] : SENT;
        float lfn[RPT], rtn[RPT];
#pragma unroll
        for (int r = 0; r < RPT; ++r) {
            lfn[r] = (x > 0)      ? s.cw[r0+r][x-1] : SENT;
            rtn[r] = (x < NX - 1) ? s.cx[r0+r][x+1] : SENT;
        }
        float4 hA = BDRY ? hmax4(dv4(nup),  dv(lfu),    dv(rtu))
                         : hmax4(nup, lfu, rtu);
        float4 hB = BDRY ? hmax4(dv4(n[0]), dv(lfn[0]), dv(rtn[0]))
                         : hmax4(n[0], lfn[0], rtn[0]);
#pragma unroll
        for (int r = 0; r < RPT; ++r) {
            float4 nx2 = (r < RPT-1) ? n[r+1]   : ndn;
            float  lfx = (r < RPT-1) ? lfn[r+1] : lfd;
            float  rtx = (r < RPT-1) ? rtn[r+1] : rtd;
            float4 hC = BDRY ? hmax4(dv4(nx2), dv(lfx), dv(rtx))
                             : hmax4(nx2, lfx, rtx);
            float4 d;
            d.x = fmaxf(e[r].x - fmaxf(hB.x, fmaxf(hA.x, hC.x)), 0.f);
            d.y = fmaxf(e[r].y - fmaxf(hB.y, fmaxf(hA.y, hC.y)), 0.f);
            d.z = fmaxf(e[r].z - fmaxf(hB.z, fmaxf(hA.z, hC.z)), 0.f);
            d.w = fmaxf(e[r].w - fmaxf(hB.w, fmaxf(hA.w, hC.w)), 0.f);
            skr[r].x += fmaxf(d.x - skr[r].x * d.x, 0.f);
            skr[r].y += fmaxf(d.y - skr[r].y * d.y, 0.f);
            skr[r].z += fmaxf(d.z - skr[r].z * d.z, 0.f);
            skr[r].w += fmaxf(d.w - skr[r].w * d.w, 0.f);
            hA = hB; hB = hC;
        }
#pragma unroll
        for (int r = 0; r < RPT; ++r) e[r] = n[r];
    }
}

__global__ void __launch_bounds__(NTH, 2)
skel_kernel(const float* __restrict__ img, float* __restrict__ sk,
            int insel, int outsel, int nsteps, int first)
{
    __shared__ SMState s;

    const float* ein  = (insel == 0) ? img : (insel == 1 ? g_e0 : g_e1);
    float*       eout = (outsel == 1) ? g_e0 : g_e1;

    const int b   = blockIdx.z;
    const int tx0 = blockIdx.x * TILE, ty0 = blockIdx.y * TILE;
    const int ocol = tx0 - HALO, orow = ty0 - HALO;
    const int t = threadIdx.x;
    const int x = t % NX, y = t / NX;
    const int r0 = y * RPT;
    const int gc0 = ocol + 4 * x;

    const float* inb = ein  + (size_t)b * HWSZ;
    float*       skb = sk   + (size_t)b * HWSZ;
    float*       eob = eout + (size_t)b * HWSZ;

    const bool bdry = (orow < 0) | (orow + 80 > IMG) | (ocol < 0) | (ocol + 80 > IMG);

    // ---- load e_k tile block into registers ----
    float4 e[RPT];
    if (!bdry) {
#pragma unroll
        for (int r = 0; r < RPT; ++r)
            e[r] = *(const float4*)(inb + (size_t)(orow + r0 + r) * IMG + gc0);
    } else {
#pragma unroll
        for (int r = 0; r < RPT; ++r) {
            int gr = orow + r0 + r;
            bool rok = (unsigned)gr < IMG;
            const float* row = inb + (size_t)(rok ? gr : 0) * IMG;
            float4 v;
            v.x = (rok && (unsigned)(gc0+0) < IMG) ? row[gc0+0] : SENT;
            v.y = (rok && (unsigned)(gc0+1) < IMG) ? row[gc0+1] : SENT;
            v.z = (rok && (unsigned)(gc0+2) < IMG) ? row[gc0+2] : SENT;
            v.w = (rok && (unsigned)(gc0+3) < IMG) ? row[gc0+3] : SENT;
            e[r] = v;
        }
    }

    // ---- sk accumulators (interior cells only are meaningful) ----
    const bool xint = (x >= 2) && (x < 18);
    float4 skr[RPT];
#pragma unroll
    for (int r = 0; r < RPT; ++r) {
        int q = r0 + r;
        if (!first && xint && q >= 8 && q < 72)
            skr[r] = *(const float4*)(skb + (size_t)(ty0 + q - 8) * IMG + (tx0 + 4*x - 8));
        else
            skr[r] = make_float4(0.f, 0.f, 0.f, 0.f);
    }

    // ---- publish e_0 edges ----
    s.rtop[y][x] = e[0];
    s.rbot[y][x] = e[RPT-1];
#pragma unroll
    for (int r = 0; r < RPT; ++r) { s.cx[r0+r][x] = e[r].x; s.cw[r0+r][x] = e[r].w; }
    __syncthreads();

    if (bdry) run_steps<true >(nsteps, s, e, skr, x, y, r0, gc0, orow);
    else      run_steps<false>(nsteps, s, e, skr, x, y, r0, gc0, orow);

    // ---- write sk and e_{+nsteps} (interior 64x64) ----
    if (xint) {
#pragma unroll
        for (int r = 0; r < RPT; ++r) {
            int q = r0 + r;
            if (q >= 8 && q < 72) {
                size_t g = (size_t)(ty0 + q - 8) * IMG + (tx0 + 4*x - 8);
                *(float4*)(skb + g) = skr[r];
                *(float4*)(eob + g) = e[r];
            }
        }
    }
}

extern "C" void kernel_launch(void* const* d_in, const int* in_sizes, int n_in,
                              void* d_out, int out_size)
{
    const float* img = (const float*)d_in[0];
    float* sk = (float*)d_out;

    dim3 grid(IMG / TILE, IMG / TILE, NB);   // 16 x 16 x 16
    dim3 block(NTH);

    // 6 launches: 7+7+7+7+7+6 = 41 deltas (e_0 .. e_41)
    skel_kernel<<<grid, block>>>(img, sk, 0, 1, 7, 1);
    skel_kernel<<<grid, block>>>(img, sk, 1, 2, 7, 0);
    skel_kernel<<<grid, block>>>(img, sk, 2, 1, 7, 0);
    skel_kernel<<<grid, block>>>(img, sk, 1, 2, 7, 0);
    skel_kernel<<<grid, block>>>(img, sk, 2, 1, 7, 0);
    skel_kernel<<<grid, block>>>(img, sk, 1, 2, 6, 0);
}

// round 6
// speedup vs baseline: 2.9139x; 1.1456x over previous
#include <cuda_runtime.h>

#define IMG   1024
#define HWSZ  (IMG*IMG)
#define NB    16
#define W     128          // padded tile width = 32 lanes * 4
#define INTW  112          // interior width (halo 8 each side)
#define NW    8            // warps per block
#define RPT   6            // rows per thread
#define H     (NW*RPT)     // 48 padded rows
#define INTH  32           // interior rows
#define NTH   256
#define SENT  1e30f
#define NEGS  (-1e30f)

// ping-pong eroded-image scratch (static device arrays: allowed)
__device__ float g_e0[(size_t)NB * HWSZ];
__device__ float g_e1[(size_t)NB * HWSZ];

struct Edges {
    float4 eT[NW][32];   // each warp's top e-row
    float4 eB[NW][32];   // bottom e-row
    float4 hT[NW][32];   // top hmax-row
    float4 hB[NW][32];   // bottom hmax-row
};

__device__ __forceinline__ float4 f4s()  { return make_float4(SENT, SENT, SENT, SENT); }
__device__ __forceinline__ float4 f4n()  { return make_float4(NEGS, NEGS, NEGS, NEGS); }

__device__ __forceinline__ float4 f4min5(float4 ce, float4 up, float4 dn, float lf, float rt) {
    float4 o;
    o.x = fminf(fminf(ce.x, fminf(up.x, dn.x)), fminf(lf,   ce.y));
    o.y = fminf(fminf(ce.y, fminf(up.y, dn.y)), fminf(ce.x, ce.z));
    o.z = fminf(fminf(ce.z, fminf(up.z, dn.z)), fminf(ce.y, ce.w));
    o.w = fminf(fminf(ce.w, fminf(up.w, dn.w)), fminf(ce.z, rt));
    return o;
}

__device__ __forceinline__ float dv(float v) { return v > 1e29f ? NEGS : v; }
__device__ __forceinline__ float4 dv4(float4 v) {
    return make_float4(dv(v.x), dv(v.y), dv(v.z), dv(v.w));
}

__device__ __forceinline__ float4 hmax4(float4 ce, float lf, float rt) {
    float m01 = fmaxf(ce.x, ce.y), m23 = fmaxf(ce.z, ce.w);
    float4 h;
    h.x = fmaxf(lf,   m01);
    h.y = fmaxf(m01,  ce.z);
    h.z = fmaxf(ce.y, m23);
    h.w = fmaxf(m23,  rt);
    return h;
}

// horizontal 3-max of one register row, neighbors via warp shuffle
template<bool BDRY>
__device__ __forceinline__ float4 hrow(float4 v, int l) {
    float lf = __shfl_up_sync(0xffffffffu, v.w, 1);
    float rt = __shfl_down_sync(0xffffffffu, v.x, 1);
    if (l == 0)  lf = SENT;
    if (l == 31) rt = SENT;
    if (BDRY) return hmax4(dv4(v), dv(lf), dv(rt));
    return hmax4(v, lf, rt);
}

template<bool BDRY>
__device__ __forceinline__ void run_steps(
    int nsteps, Edges* eb, float4 (&e)[RPT], float4 (&skr)[RPT],
    int l, int w, int gc0, int orow, int r0)
{
    // out-of-image masks (only used when BDRY)
    bool rowbad[RPT];
    bool cb0 = false, cb1 = false, cb2 = false, cb3 = false;
    if (BDRY) {
#pragma unroll
        for (int r = 0; r < RPT; ++r)
            rowbad[r] = (unsigned)(orow + r0 + r) >= IMG;
        cb0 = (unsigned)(gc0 + 0) >= IMG;
        cb1 = (unsigned)(gc0 + 1) >= IMG;
        cb2 = (unsigned)(gc0 + 2) >= IMG;
        cb3 = (unsigned)(gc0 + 3) >= IMG;
    }

    for (int step = 0; step < nsteps; ++step) {
        Edges* rd = &eb[step & 1];
        Edges* wr = &eb[(step & 1) ^ 1];

        // ---- erode: neighbors above/below via smem (warp edges), l/r via shuffle ----
        float4 up = (w > 0)      ? rd->eB[w - 1][l] : f4s();
        float4 dn = (w < NW - 1) ? rd->eT[w + 1][l] : f4s();

        float4 n[RPT];
#pragma unroll
        for (int r = 0; r < RPT; ++r) {
            float lf = __shfl_up_sync(0xffffffffu, e[r].w, 1);
            float rt = __shfl_down_sync(0xffffffffu, e[r].x, 1);
            if (l == 0)  lf = SENT;
            if (l == 31) rt = SENT;
            float4 u = (r == 0)       ? up : e[r - 1];
            float4 d = (r == RPT - 1) ? dn : e[r + 1];
            n[r] = f4min5(e[r], u, d, lf, rt);
        }

        if (BDRY) {
            // re-impose +inf sentinel at out-of-image cells (exact erode semantics)
#pragma unroll
            for (int r = 0; r < RPT; ++r) {
                if (rowbad[r]) n[r] = f4s();
                else {
                    if (cb0) n[r].x = SENT;
                    if (cb1) n[r].y = SENT;
                    if (cb2) n[r].z = SENT;
                    if (cb3) n[r].w = SENT;
                }
            }
        }

        // ---- publish new edges + boundary hmax rows ----
        float4 hm0 = hrow<BDRY>(n[0],       l);
        float4 hm5 = hrow<BDRY>(n[RPT - 1], l);
        wr->eT[w][l] = n[0];
        wr->eB[w][l] = n[RPT - 1];
        wr->hT[w][l] = hm0;
        wr->hB[w][l] = hm5;
        __syncthreads();

        // ---- dilate (rolling vertical 3-max of hmax rows) + delta + sk ----
        float4 hU = (w > 0)      ? wr->hB[w - 1][l] : f4n();
        float4 hD = (w < NW - 1) ? wr->hT[w + 1][l] : f4n();

        float4 hA = hU, hB = hm0;
#pragma unroll
        for (int r = 0; r < RPT; ++r) {
            float4 hC;
            if (r == RPT - 2)      hC = hm5;
            else if (r == RPT - 1) hC = hD;
            else                   hC = hrow<BDRY>(n[r + 1], l);

            float vx = fmaxf(hB.x, fmaxf(hA.x, hC.x));
            float vy = fmaxf(hB.y, fmaxf(hA.y, hC.y));
            float vz = fmaxf(hB.z, fmaxf(hA.z, hC.z));
            float vw = fmaxf(hB.w, fmaxf(hA.w, hC.w));

            float dx = fmaxf(e[r].x - vx, 0.f);
            float dy = fmaxf(e[r].y - vy, 0.f);
            float dz = fmaxf(e[r].z - vz, 0.f);
            float dw = fmaxf(e[r].w - vw, 0.f);

            skr[r].x += fmaxf(dx - skr[r].x * dx, 0.f);
            skr[r].y += fmaxf(dy - skr[r].y * dy, 0.f);
            skr[r].z += fmaxf(dz - skr[r].z * dz, 0.f);
            skr[r].w += fmaxf(dw - skr[r].w * dw, 0.f);

            hA = hB; hB = hC;
            e[r] = n[r];
        }
        // no trailing sync needed: next step's reads hit the buffer written
        // before this step's sync; next step's writes hit the other parity.
    }
}

__global__ void __launch_bounds__(NTH, 2)
skel_kernel(const float* __restrict__ img, float* __restrict__ sk,
            int insel, int outsel, int nsteps, int first)
{
    __shared__ Edges eb[2];   // 32 KB

    const float* ein  = (insel == 0) ? img : (insel == 1 ? g_e0 : g_e1);
    float*       eout = (outsel == 1) ? g_e0 : g_e1;

    const int b = blockIdx.z;
    int tx0 = blockIdx.x * INTW;
    if (tx0 > IMG - INTW) tx0 = IMG - INTW;     // clamped overlap tile (idempotent)
    const int ty0 = blockIdx.y * INTH;
    const int ocol = tx0 - 8, orow = ty0 - 8;

    const int t = threadIdx.x;
    const int l = t & 31, w = t >> 5;
    const int r0 = w * RPT;
    const int gc0 = ocol + 4 * l;

    const float* inb = ein  + (size_t)b * HWSZ;
    float*       skb = sk   + (size_t)b * HWSZ;
    float*       eob = eout + (size_t)b * HWSZ;

    const bool bdry = (orow < 0) | (orow + H > IMG) | (ocol < 0) | (ocol + W > IMG);

    // ---- load tile block into registers ----
    float4 e[RPT];
    if (!bdry) {
#pragma unroll
        for (int r = 0; r < RPT; ++r)
            e[r] = *(const float4*)(inb + (size_t)(orow + r0 + r) * IMG + gc0);
    } else {
#pragma unroll
        for (int r = 0; r < RPT; ++r) {
            int gr = orow + r0 + r;
            bool rok = (unsigned)gr < IMG;
            const float* row = inb + (size_t)(rok ? gr : 0) * IMG;
            float4 v;
            v.x = (rok && (unsigned)(gc0 + 0) < IMG) ? row[gc0 + 0] : SENT;
            v.y = (rok && (unsigned)(gc0 + 1) < IMG) ? row[gc0 + 1] : SENT;
            v.z = (rok && (unsigned)(gc0 + 2) < IMG) ? row[gc0 + 2] : SENT;
            v.w = (rok && (unsigned)(gc0 + 3) < IMG) ? row[gc0 + 3] : SENT;
            e[r] = v;
        }
    }

    // ---- sk accumulators (interior lanes 2..29, interior rows 8..39) ----
    const bool xint = (l >= 2) && (l < 30);
    float4 skr[RPT];
#pragma unroll
    for (int r = 0; r < RPT; ++r) {
        int q = r0 + r;
        if (!first && xint && q >= 8 && q < 8 + INTH)
            skr[r] = *(const float4*)(skb + (size_t)(ty0 + q - 8) * IMG + (tx0 + 4 * (l - 2)));
        else
            skr[r] = make_float4(0.f, 0.f, 0.f, 0.f);
    }

    // ---- publish e_0 edges into parity 0 ----
    eb[0].eT[w][l] = e[0];
    eb[0].eB[w][l] = e[RPT - 1];
    __syncthreads();

    if (bdry) run_steps<true >(nsteps, eb, e, skr, l, w, gc0, orow, r0);
    else      run_steps<false>(nsteps, eb, e, skr, l, w, gc0, orow, r0);

    // ---- write sk and final eroded image (interior 112x32) ----
    if (xint) {
#pragma unroll
        for (int r = 0; r < RPT; ++r) {
            int q = r0 + r;
            if (q >= 8 && q < 8 + INTH) {
                size_t g = (size_t)(ty0 + q - 8) * IMG + (tx0 + 4 * (l - 2));
                *(float4*)(skb + g) = skr[r];
                *(float4*)(eob + g) = e[r];
            }
        }
    }
}

extern "C" void kernel_launch(void* const* d_in, const int* in_sizes, int n_in,
                              void* d_out, int out_size)
{
    const float* img = (const float*)d_in[0];
    float* sk = (float*)d_out;

    dim3 grid((IMG + INTW - 1) / INTW, IMG / INTH, NB);   // 10 x 32 x 16
    dim3 block(NTH);

    // 6 launches: 7+7+7+7+7+6 = 41 deltas (e_0 .. e_41)
    skel_kernel<<<grid, block>>>(img, sk, 0, 1, 7, 1);
    skel_kernel<<<grid, block>>>(img, sk, 1, 2, 7, 0);
    skel_kernel<<<grid, block>>>(img, sk, 2, 1, 7, 0);
    skel_kernel<<<grid, block>>>(img, sk, 1, 2, 7, 0);
    skel_kernel<<<grid, block>>>(img, sk, 2, 1, 7, 0);
    skel_kernel<<<grid, block>>>(img, sk, 1, 2, 6, 0);
}